// round 1
// baseline (speedup 1.0000x reference)
#include <cuda_runtime.h>

// SE(3) exp(xi) composed with initial poses:
//   T = [R(omega) t; 0 0 0 1],  out = T @ P
// out_row_i = R[i][0]*P0 + R[i][1]*P1 + R[i][2]*P2 + t[i]*P3   (i<3)
// out_row_3 = P3
#define EPS_THETA 1e-6f

__device__ __forceinline__ float4 f4_fma(float a, float4 x, float4 acc) {
    acc.x = fmaf(a, x.x, acc.x);
    acc.y = fmaf(a, x.y, acc.y);
    acc.z = fmaf(a, x.z, acc.z);
    acc.w = fmaf(a, x.w, acc.w);
    return acc;
}

__device__ __forceinline__ float4 f4_scale(float a, float4 x) {
    return make_float4(a * x.x, a * x.y, a * x.z, a * x.w);
}

__global__ void __launch_bounds__(256) se3_compose_kernel(
    const float* __restrict__ xi,       // [N, 6]
    const float4* __restrict__ poses,   // [N, 4] rows of float4
    float4* __restrict__ out,           // [N, 4] rows of float4
    int n)
{
    int i = blockIdx.x * blockDim.x + threadIdx.x;
    if (i >= n) return;

    // xi row: 24-byte aligned -> three float2 loads
    const float2* xi2 = reinterpret_cast<const float2*>(xi + (size_t)i * 6);
    float2 a = xi2[0];   // tx, ty
    float2 b = xi2[1];   // tz, wx
    float2 c2 = xi2[2];  // wy, wz
    float tx = a.x, ty = a.y, tz = b.x;
    float wx = b.y, wy = c2.x, wz = c2.y;

    float theta2 = wx * wx + wy * wy + wz * wz;
    float theta  = sqrtf(theta2);
    bool small   = theta < EPS_THETA;

    float R00, R01, R02, R10, R11, R12, R20, R21, R22;
    if (small) {
        // R = I + skew(omega)
        R00 = 1.0f; R01 = -wz;  R02 =  wy;
        R10 =  wz;  R11 = 1.0f; R12 = -wx;
        R20 = -wy;  R21 =  wx;  R22 = 1.0f;
    } else {
        float inv_t = 1.0f / theta;
        float kx = wx * inv_t, ky = wy * inv_t, kz = wz * inv_t;
        float s, cth;
        __sincosf(theta, &s, &cth);           // fast path; refine below if needed
        s   = sinf(theta);
        cth = cosf(theta);
        float c = 1.0f - cth;
        // K^2 = k k^T - I (|k| = 1)
        R00 = 1.0f + c * (kx * kx - 1.0f);
        R11 = 1.0f + c * (ky * ky - 1.0f);
        R22 = 1.0f + c * (kz * kz - 1.0f);
        float cxy = c * kx * ky, cxz = c * kx * kz, cyz = c * ky * kz;
        float skx = s * kx, sky = s * ky, skz = s * kz;
        R01 = cxy - skz;  R02 = cxz + sky;
        R10 = cxy + skz;  R12 = cyz - skx;
        R20 = cxz - sky;  R21 = cyz + skx;
    }

    const float4* P = poses + (size_t)i * 4;
    float4 p0 = P[0];
    float4 p1 = P[1];
    float4 p2 = P[2];
    float4 p3 = P[3];

    float4 o0 = f4_scale(R00, p0);
    o0 = f4_fma(R01, p1, o0); o0 = f4_fma(R02, p2, o0); o0 = f4_fma(tx, p3, o0);
    float4 o1 = f4_scale(R10, p0);
    o1 = f4_fma(R11, p1, o1); o1 = f4_fma(R12, p2, o1); o1 = f4_fma(ty, p3, o1);
    float4 o2 = f4_scale(R20, p0);
    o2 = f4_fma(R21, p1, o2); o2 = f4_fma(R22, p2, o2); o2 = f4_fma(tz, p3, o2);

    float4* O = out + (size_t)i * 4;
    O[0] = o0;
    O[1] = o1;
    O[2] = o2;
    O[3] = p3;
}

extern "C" void kernel_launch(void* const* d_in, const int* in_sizes, int n_in,
                              void* d_out, int out_size) {
    const float*  xi    = (const float*)d_in[0];   // [N,6]
    const float4* poses = (const float4*)d_in[1];  // [N,4,4] as [N,4] float4
    float4*       out   = (float4*)d_out;
    int n = in_sizes[0] / 6;
    int threads = 256;
    int blocks = (n + threads - 1) / threads;
    se3_compose_kernel<<<blocks, threads>>>(xi, poses, out, n);
}

// round 3
// speedup vs baseline: 1.1054x; 1.1054x over previous
#include <cuda_runtime.h>

// SE(3) exp(xi) composed with initial poses, 2 poses per thread (split-grid
// pairing: i0 = t, i1 = t + H) so every memory instruction is unit-stride
// coalesced while per-warp MLP doubles.
#define EPS_THETA 1e-6f

__device__ __forceinline__ float4 f4_fma(float a, float4 x, float4 acc) {
    acc.x = fmaf(a, x.x, acc.x);
    acc.y = fmaf(a, x.y, acc.y);
    acc.z = fmaf(a, x.z, acc.z);
    acc.w = fmaf(a, x.w, acc.w);
    return acc;
}
__device__ __forceinline__ float4 f4_scale(float a, float4 x) {
    return make_float4(a * x.x, a * x.y, a * x.z, a * x.w);
}

struct R9 { float R00,R01,R02,R10,R11,R12,R20,R21,R22; };

__device__ __forceinline__ R9 rodrigues(float wx, float wy, float wz) {
    R9 r;
    float theta2 = wx*wx + wy*wy + wz*wz;
    float theta  = sqrtf(theta2);
    if (theta < EPS_THETA) {
        r.R00 = 1.0f; r.R01 = -wz;  r.R02 =  wy;
        r.R10 =  wz;  r.R11 = 1.0f; r.R12 = -wx;
        r.R20 = -wy;  r.R21 =  wx;  r.R22 = 1.0f;
    } else {
        float inv_t = 1.0f / theta;
        float kx = wx*inv_t, ky = wy*inv_t, kz = wz*inv_t;
        float s   = sinf(theta);
        float c   = 1.0f - cosf(theta);
        r.R00 = 1.0f + c * (kx*kx - 1.0f);
        r.R11 = 1.0f + c * (ky*ky - 1.0f);
        r.R22 = 1.0f + c * (kz*kz - 1.0f);
        float cxy = c*kx*ky, cxz = c*kx*kz, cyz = c*ky*kz;
        float skx = s*kx, sky = s*ky, skz = s*kz;
        r.R01 = cxy - skz;  r.R02 = cxz + sky;
        r.R10 = cxy + skz;  r.R12 = cyz - skx;
        r.R20 = cxz - sky;  r.R21 = cyz + skx;
    }
    return r;
}

__global__ void __launch_bounds__(256) se3_compose2_kernel(
    const float*  __restrict__ xi,      // [N, 6]
    const float4* __restrict__ poses,   // [N, 4] rows of float4
    float4*       __restrict__ out,     // [N, 4] rows of float4
    int H, int n)
{
    int t = blockIdx.x * blockDim.x + threadIdx.x;
    if (t >= H) return;
    int i0 = t;
    int i1 = t + H;
    bool has1 = (i1 < n);

    // ---- front-batched loads (maximize MLP) ----
    const float2* xa = reinterpret_cast<const float2*>(xi + (size_t)i0 * 6);
    float2 a0 = __ldcs(xa + 0);
    float2 a1 = __ldcs(xa + 1);
    float2 a2 = __ldcs(xa + 2);

    const float2* xb = reinterpret_cast<const float2*>(xi + (size_t)i1 * 6);
    float2 b0, b1, b2;
    if (has1) { b0 = __ldcs(xb + 0); b1 = __ldcs(xb + 1); b2 = __ldcs(xb + 2); }

    const float4* Pa = poses + (size_t)i0 * 4;
    float4 pa0 = __ldcs(Pa + 0);
    float4 pa1 = __ldcs(Pa + 1);
    float4 pa2 = __ldcs(Pa + 2);
    float4 pa3 = __ldcs(Pa + 3);

    const float4* Pb = poses + (size_t)i1 * 4;
    float4 pb0, pb1, pb2, pb3;
    if (has1) {
        pb0 = __ldcs(Pb + 0);
        pb1 = __ldcs(Pb + 1);
        pb2 = __ldcs(Pb + 2);
        pb3 = __ldcs(Pb + 3);
    }

    // ---- pose 0 ----
    {
        float tx = a0.x, ty = a0.y, tz = a1.x;
        R9 r = rodrigues(a1.y, a2.x, a2.y);
        float4 o0 = f4_scale(r.R00, pa0);
        o0 = f4_fma(r.R01, pa1, o0); o0 = f4_fma(r.R02, pa2, o0); o0 = f4_fma(tx, pa3, o0);
        float4 o1 = f4_scale(r.R10, pa0);
        o1 = f4_fma(r.R11, pa1, o1); o1 = f4_fma(r.R12, pa2, o1); o1 = f4_fma(ty, pa3, o1);
        float4 o2 = f4_scale(r.R20, pa0);
        o2 = f4_fma(r.R21, pa1, o2); o2 = f4_fma(r.R22, pa2, o2); o2 = f4_fma(tz, pa3, o2);
        float4* O = out + (size_t)i0 * 4;
        __stcs(O + 0, o0);
        __stcs(O + 1, o1);
        __stcs(O + 2, o2);
        __stcs(O + 3, pa3);
    }

    // ---- pose 1 ----
    if (has1) {
        float tx = b0.x, ty = b0.y, tz = b1.x;
        R9 r = rodrigues(b1.y, b2.x, b2.y);
        float4 o0 = f4_scale(r.R00, pb0);
        o0 = f4_fma(r.R01, pb1, o0); o0 = f4_fma(r.R02, pb2, o0); o0 = f4_fma(tx, pb3, o0);
        float4 o1 = f4_scale(r.R10, pb0);
        o1 = f4_fma(r.R11, pb1, o1); o1 = f4_fma(r.R12, pb2, o1); o1 = f4_fma(ty, pb3, o1);
        float4 o2 = f4_scale(r.R20, pb0);
        o2 = f4_fma(r.R21, pb1, o2); o2 = f4_fma(r.R22, pb2, o2); o2 = f4_fma(tz, pb3, o2);
        float4* O = out + (size_t)i1 * 4;
        __stcs(O + 0, o0);
        __stcs(O + 1, o1);
        __stcs(O + 2, o2);
        __stcs(O + 3, pb3);
    }
}

extern "C" void kernel_launch(void* const* d_in, const int* in_sizes, int n_in,
                              void* d_out, int out_size) {
    const float*  xi    = (const float*)d_in[0];   // [N,6]
    const float4* poses = (const float4*)d_in[1];  // [N,4,4] as rows of float4
    float4*       out   = (float4*)d_out;
    int n = in_sizes[0] / 6;
    int H = (n + 1) / 2;   // pairing: thread t -> poses t and t+H
    int threads = 256;
    int blocks = (H + threads - 1) / threads;
    se3_compose2_kernel<<<blocks, threads>>>(xi, poses, out, H, n);
}